// round 2
// baseline (speedup 1.0000x reference)
#include <cuda_runtime.h>
#include <math.h>

#define IMG 256
#define NVERT 642
#define NFACE 1280
#define NBATCH 2
#define SHARP (2.0f * (float)IMG)
#define CHUNK 640   // faces per smem chunk (640*3*16B = 30720B smem)

// Per-face data: 3 x float4 = [A1,B1,C1,A2][B2,C2,A3,B3][C3,orient,0,0]
__device__ __align__(16) float4 g_face4[NBATCH * NFACE * 3];

__device__ __forceinline__ void edge_coeff(float ax, float ay, float bx, float by,
                                           float& A, float& B, float& C) {
    float ex = bx - ax;
    float ey = by - ay;
    float il = rsqrtf(ex * ex + ey * ey + 1e-12f);
    float exn = ex * il;
    float eyn = ey * il;
    A = -eyn;                    // coeff of px
    B = exn;                     // coeff of py
    C = eyn * ax - exn * ay;     // constant
}

__global__ void prep_kernel(const float* __restrict__ verts,
                            const int* __restrict__ faces,
                            const float* __restrict__ cams) {
    const int b = blockIdx.x;
    __shared__ float sx[NVERT];
    __shared__ float sy[NVERT];

    const float* cam = cams + b * 7;
    float s  = cam[0];
    float tx = cam[1];
    float ty = cam[2];
    float qw = cam[3], qx = cam[4], qy = cam[5], qz = cam[6];
    float qn = rsqrtf(qw * qw + qx * qx + qy * qy + qz * qz);
    qw *= qn; qx *= qn; qy *= qn; qz *= qn;

    // Rotation matrix rows 0 and 1 (z row unused for silhouette)
    float r00 = 1.f - 2.f * (qy * qy + qz * qz);
    float r01 = 2.f * (qx * qy - qw * qz);
    float r02 = 2.f * (qx * qz + qw * qy);
    float r10 = 2.f * (qx * qy + qw * qz);
    float r11 = 1.f - 2.f * (qx * qx + qz * qz);
    float r12 = 2.f * (qy * qz - qw * qx);

    for (int n = threadIdx.x; n < NVERT; n += blockDim.x) {
        const float* v = verts + (size_t)(b * NVERT + n) * 3;
        float X = v[0], Y = v[1], Z = v[2];
        float xr = r00 * X + r01 * Y + r02 * Z;
        float yr = r10 * X + r11 * Y + r12 * Z;
        sx[n] = s * xr + tx;          // x
        sy[n] = -(s * yr + ty);       // y with [1,-1,1] flip folded in
    }
    __syncthreads();

    for (int f = threadIdx.x; f < NFACE; f += blockDim.x) {
        const int* fi = faces + (size_t)(b * NFACE + f) * 3;
        int i0 = fi[0], i1 = fi[1], i2 = fi[2];
        float x0 = sx[i0], y0 = sy[i0];
        float x1 = sx[i1], y1 = sy[i1];
        float x2 = sx[i2], y2 = sy[i2];

        float area2 = (x1 - x0) * (y2 - y0) - (y1 - y0) * (x2 - x0);
        float orient = (area2 > 0.f) ? 1.f : ((area2 < 0.f) ? -1.f : 0.f);

        float A1, B1, C1, A2, B2, C2, A3, B3, C3;
        edge_coeff(x0, y0, x1, y1, A1, B1, C1);
        edge_coeff(x1, y1, x2, y2, A2, B2, C2);
        edge_coeff(x2, y2, x0, y0, A3, B3, C3);

        float4* dst = &g_face4[(size_t)(b * NFACE + f) * 3];
        dst[0] = make_float4(A1, B1, C1, A2);
        dst[1] = make_float4(B2, C2, A3, B3);
        dst[2] = make_float4(C3, orient, 0.f, 0.f);
    }
}

// 128 threads/block. Each block: 2 rows of 256 px -> 512 px, 4 px/thread.
// Grid: (IMG*IMG / 512, NBATCH) = (128, 2).
__global__ __launch_bounds__(128) void render_kernel(float* __restrict__ out) {
    const int b    = blockIdx.y;
    const int tile = blockIdx.x;
    const int t    = threadIdx.x;

    const int row = tile * 2 + (t >> 6);
    const int xs  = (t & 63) * 4;

    const float inv = 2.0f / (float)IMG;
    const float py = ((float)row + 0.5f) * inv - 1.0f;

    float px[4], acc[4];
#pragma unroll
    for (int p = 0; p < 4; ++p) {
        px[p]  = ((float)(xs + p) + 0.5f) * inv - 1.0f;
        acc[p] = -3.402823466e+38f;
    }

    __shared__ __align__(16) float4 sf[CHUNK * 3];
    const float4* gsrc = &g_face4[(size_t)b * NFACE * 3];

    for (int c = 0; c < NFACE; c += CHUNK) {
        // Cooperative load of this chunk's face data into smem
        for (int i = t; i < CHUNK * 3; i += 128) {
            sf[i] = gsrc[(size_t)c * 3 + i];
        }
        __syncthreads();

#pragma unroll 2
        for (int f = 0; f < CHUNK; ++f) {
            float4 e0 = sf[f * 3 + 0];
            float4 e1 = sf[f * 3 + 1];
            float4 e2 = sf[f * 3 + 2];

            float A1 = e0.x, A2 = e0.w, A3 = e1.z;
            float t1 = fmaf(e0.y, py, e0.z);   // B1*py + C1
            float t2 = fmaf(e1.x, py, e1.y);   // B2*py + C2
            float t3 = fmaf(e1.w, py, e2.x);   // B3*py + C3
            float o  = e2.y;

#pragma unroll
            for (int p = 0; p < 4; ++p) {
                float d1 = fmaf(A1, px[p], t1);
                float d2 = fmaf(A2, px[p], t2);
                float d3 = fmaf(A3, px[p], t3);
                float dm = fminf(fminf(d1, d2), d3);
                acc[p] = fmaxf(acc[p], o * dm);
            }
        }
        __syncthreads();
    }

    // sigmoid(SHARP * acc) — hoisted out of the face loop (monotonicity)
    float4 res;
    res.x = 1.0f / (1.0f + expf(-SHARP * acc[0]));
    res.y = 1.0f / (1.0f + expf(-SHARP * acc[1]));
    res.z = 1.0f / (1.0f + expf(-SHARP * acc[2]));
    res.w = 1.0f / (1.0f + expf(-SHARP * acc[3]));

    float4* op = (float4*)(out + (size_t)b * IMG * IMG + (size_t)row * IMG + xs);
    *op = res;
}

extern "C" void kernel_launch(void* const* d_in, const int* in_sizes, int n_in,
                              void* d_out, int out_size) {
    const float* verts = (const float*)d_in[0];  // [2, 642, 3] f32
    const int*   faces = (const int*)d_in[1];    // [2, 1280, 3] i32
    const float* cams  = (const float*)d_in[2];  // [2, 7] f32
    float* out = (float*)d_out;                  // [2, 256, 256] f32

    prep_kernel<<<NBATCH, 256>>>(verts, faces, cams);
    render_kernel<<<dim3(IMG * IMG / 512, NBATCH), 128>>>(out);
}

// round 3
// speedup vs baseline: 5.5846x; 5.5846x over previous
#include <cuda_runtime.h>
#include <math.h>

#define IMG 256
#define NVERT 642
#define NFACE 1280
#define NBATCH 2
#define SHARP (2.0f * (float)IMG)
#define FCHUNK 32
#define TAU 0.04f
#define FPT 5          // faces per thread in prep (256*5 = 1280)

// Sorted per-face data: 3 x float4 = [A1,B1,C1,A2][B2,C2,A3,B3][C3,pad,pad,pad]
// Faces [0, M): orient<0, coefficients NEGATED  -> contribution = max(d1,d2,d3)
// Faces [M, NFACE): orient>=0 (zero-area stored as all-zero) -> contribution = min(d1,d2,d3)
__device__ __align__(16) float4 g_face4[NBATCH * NFACE * 3];
__device__ int g_M[NBATCH];

__device__ __forceinline__ void edge_coeff(float ax, float ay, float bx, float by,
                                           float& A, float& B, float& C) {
    float ex = bx - ax;
    float ey = by - ay;
    float il = rsqrtf(ex * ex + ey * ey + 1e-12f);
    float exn = ex * il;
    float eyn = ey * il;
    A = -eyn;                    // coeff of px
    B = exn;                     // coeff of py
    C = eyn * ax - exn * ay;     // constant
}

__global__ void prep_kernel(const float* __restrict__ verts,
                            const int* __restrict__ faces,
                            const float* __restrict__ cams) {
    const int b = blockIdx.x;
    const int t = threadIdx.x;
    __shared__ float sx[NVERT];
    __shared__ float sy[NVERT];
    __shared__ int scan[256];

    const float* cam = cams + b * 7;
    float s  = cam[0];
    float tx = cam[1];
    float ty = cam[2];
    float qw = cam[3], qx = cam[4], qy = cam[5], qz = cam[6];
    float qn = rsqrtf(qw * qw + qx * qx + qy * qy + qz * qz);
    qw *= qn; qx *= qn; qy *= qn; qz *= qn;

    float r00 = 1.f - 2.f * (qy * qy + qz * qz);
    float r01 = 2.f * (qx * qy - qw * qz);
    float r02 = 2.f * (qx * qz + qw * qy);
    float r10 = 2.f * (qx * qy + qw * qz);
    float r11 = 1.f - 2.f * (qx * qx + qz * qz);
    float r12 = 2.f * (qy * qz - qw * qx);

    for (int n = t; n < NVERT; n += blockDim.x) {
        const float* v = verts + (size_t)(b * NVERT + n) * 3;
        float X = v[0], Y = v[1], Z = v[2];
        float xr = r00 * X + r01 * Y + r02 * Z;
        float yr = r10 * X + r11 * Y + r12 * Z;
        sx[n] = s * xr + tx;          // x
        sy[n] = -(s * yr + ty);       // y with [1,-1,1] flip folded in
    }
    __syncthreads();

    // Pass 1: classify this thread's FPT consecutive faces (deterministic, no atomics)
    const int base = t * FPT;
    bool isMinus[FPT];
    bool isZero[FPT];
    int cnt = 0;
    #pragma unroll
    for (int k = 0; k < FPT; ++k) {
        const int* fi = faces + (size_t)(b * NFACE + base + k) * 3;
        int i0 = fi[0], i1 = fi[1], i2 = fi[2];
        float x0 = sx[i0], y0 = sy[i0];
        float x1 = sx[i1], y1 = sy[i1];
        float x2 = sx[i2], y2 = sy[i2];
        float area2 = (x1 - x0) * (y2 - y0) - (y1 - y0) * (x2 - x0);
        isMinus[k] = (area2 < 0.f);
        isZero[k]  = (area2 == 0.f);
        cnt += isMinus[k] ? 1 : 0;
    }
    scan[t] = cnt;
    __syncthreads();
    // Hillis-Steele inclusive scan over 256 thread counts
    for (int off = 1; off < 256; off <<= 1) {
        int v = scan[t];
        int w = (t >= off) ? scan[t - off] : 0;
        __syncthreads();
        scan[t] = v + w;
        __syncthreads();
    }
    const int minusBefore = scan[t] - cnt;   // exclusive prefix
    const int M = scan[255];
    if (t == 0) g_M[b] = M;

    // Pass 2: compute coefficients and write to sorted position
    int mloc = 0, ploc = 0;
    const int plusBefore = base - minusBefore;
    #pragma unroll
    for (int k = 0; k < FPT; ++k) {
        const int* fi = faces + (size_t)(b * NFACE + base + k) * 3;
        int i0 = fi[0], i1 = fi[1], i2 = fi[2];
        float x0 = sx[i0], y0 = sy[i0];
        float x1 = sx[i1], y1 = sy[i1];
        float x2 = sx[i2], y2 = sy[i2];

        float A1, B1, C1, A2, B2, C2, A3, B3, C3;
        edge_coeff(x0, y0, x1, y1, A1, B1, C1);
        edge_coeff(x1, y1, x2, y2, A2, B2, C2);
        edge_coeff(x2, y2, x0, y0, A3, B3, C3);

        int pos;
        float sgn;
        if (isMinus[k]) {
            pos = minusBefore + (mloc++);
            sgn = -1.f;
        } else {
            pos = M + plusBefore + (ploc++);
            sgn = isZero[k] ? 0.f : 1.f;   // zero-area -> all-zero record -> contributes 0
        }
        float4* dst = &g_face4[(size_t)(b * NFACE + pos) * 3];
        dst[0] = make_float4(sgn * A1, sgn * B1, sgn * C1, sgn * A2);
        dst[1] = make_float4(sgn * B2, sgn * C2, sgn * A3, sgn * B3);
        dst[2] = make_float4(sgn * C3, 0.f, 0.f, 0.f);
    }
}

// 128 threads/block; block covers 2 rows (512 px), 4 px/thread. Grid (128, NBATCH).
__global__ __launch_bounds__(128) void render_kernel(float* __restrict__ out) {
    const int b    = blockIdx.y;
    const int tile = blockIdx.x;
    const int t    = threadIdx.x;

    const int row = tile * 2 + (t >> 6);
    const int xs  = (t & 63) * 4;

    const float inv = 2.0f / (float)IMG;
    const float py = ((float)row + 0.5f) * inv - 1.0f;

    float px[4], acc[4];
#pragma unroll
    for (int p = 0; p < 4; ++p) {
        px[p]  = ((float)(xs + p) + 0.5f) * inv - 1.0f;
        acc[p] = -3.402823466e+38f;
    }

    __shared__ __align__(16) float4 sf[FCHUNK * 3];
    const float4* gsrc = &g_face4[(size_t)b * NFACE * 3];
    const int M = g_M[b];

    bool done = false;
    for (int c = 0; c < NFACE; c += FCHUNK) {
        const int n = min(FCHUNK, NFACE - c);
        // Cooperative stage of this chunk (all warps participate, even if done)
        for (int i = t; i < n * 3; i += 128) {
            sf[i] = gsrc[(size_t)(c) * 3 + i];
        }
        __syncthreads();

        if (!done) {
            const int hiA = max(0, min(M - c, n));   // faces [0,hiA): max-form (inverted)
            #pragma unroll 2
            for (int f = 0; f < hiA; ++f) {
                float4 e0 = sf[f * 3 + 0];
                float4 e1 = sf[f * 3 + 1];
                float C3 = sf[f * 3 + 2].x;
                float t1 = fmaf(e0.y, py, e0.z);
                float t2 = fmaf(e1.x, py, e1.y);
                float t3 = fmaf(e1.w, py, C3);
                #pragma unroll
                for (int p = 0; p < 4; ++p) {
                    float d1 = fmaf(e0.x, px[p], t1);
                    float d2 = fmaf(e0.w, px[p], t2);
                    float d3 = fmaf(e1.z, px[p], t3);
                    float dm = fmaxf(fmaxf(d1, d2), d3);
                    acc[p] = fmaxf(acc[p], dm);
                }
            }
            #pragma unroll 2
            for (int f = hiA; f < n; ++f) {          // min-form (normal orientation)
                float4 e0 = sf[f * 3 + 0];
                float4 e1 = sf[f * 3 + 1];
                float C3 = sf[f * 3 + 2].x;
                float t1 = fmaf(e0.y, py, e0.z);
                float t2 = fmaf(e1.x, py, e1.y);
                float t3 = fmaf(e1.w, py, C3);
                #pragma unroll
                for (int p = 0; p < 4; ++p) {
                    float d1 = fmaf(e0.x, px[p], t1);
                    float d2 = fmaf(e0.w, px[p], t2);
                    float d3 = fmaf(e1.z, px[p], t3);
                    float dm = fminf(fminf(d1, d2), d3);
                    acc[p] = fmaxf(acc[p], dm);
                }
            }
            // Saturation: sigmoid(SHARP*acc) within 1.3e-9 of 1 for acc >= TAU;
            // later faces can only raise the max -> output unchanged beyond 1e-9.
            float m = fminf(fminf(acc[0], acc[1]), fminf(acc[2], acc[3]));
            done = (__all_sync(0xffffffffu, m >= TAU) != 0);
        }
        // Block-collective exit; also the barrier protecting sf reuse next iter
        if (__syncthreads_and(done ? 1 : 0)) break;
    }

    float4 res;
    res.x = 1.0f / (1.0f + expf(-SHARP * acc[0]));
    res.y = 1.0f / (1.0f + expf(-SHARP * acc[1]));
    res.z = 1.0f / (1.0f + expf(-SHARP * acc[2]));
    res.w = 1.0f / (1.0f + expf(-SHARP * acc[3]));

    float4* op = (float4*)(out + (size_t)b * IMG * IMG + (size_t)row * IMG + xs);
    *op = res;
}

extern "C" void kernel_launch(void* const* d_in, const int* in_sizes, int n_in,
                              void* d_out, int out_size) {
    const float* verts = (const float*)d_in[0];  // [2, 642, 3] f32
    const int*   faces = (const int*)d_in[1];    // [2, 1280, 3] i32
    const float* cams  = (const float*)d_in[2];  // [2, 7] f32
    float* out = (float*)d_out;                  // [2, 256, 256] f32

    prep_kernel<<<NBATCH, 256>>>(verts, faces, cams);
    render_kernel<<<dim3(IMG * IMG / 512, NBATCH), 128>>>(out);
}

// round 4
// speedup vs baseline: 7.8065x; 1.3978x over previous
#include <cuda_runtime.h>
#include <math.h>

#define IMG 256
#define NVERT 642
#define NFACE 1280
#define NBATCH 2
#define SHARP (2.0f * (float)IMG)
#define FCHUNK 32
#define TAU 0.04f   // sigmoid(SHARP*TAU) >= 1 - 1.3e-9: later faces can't change output

// Fully fused: vertex transform + lazy per-chunk edge coefficients + pixel max.
// Grid (IMG*IMG/512, NBATCH); block 128 threads = 2 rows x 64 threads x 4 px.
__global__ __launch_bounds__(128) void fused_kernel(const float* __restrict__ verts,
                                                    const int* __restrict__ faces,
                                                    const float* __restrict__ cams,
                                                    float* __restrict__ out) {
    const int b    = blockIdx.y;
    const int tile = blockIdx.x;
    const int t    = threadIdx.x;

    __shared__ float sx[NVERT];
    __shared__ float sy[NVERT];
    __shared__ __align__(16) float4 sf0[FCHUNK];   // A1,B1,C1,A2
    __shared__ __align__(16) float4 sf1[FCHUNK];   // B2,C2,A3,B3
    __shared__ __align__(8)  float2 sf2[FCHUNK];   // C3, orient

    // ---- camera transform constants (all threads redundantly; broadcast loads)
    const float* cam = cams + b * 7;
    float s  = cam[0];
    float tx = cam[1];
    float ty = cam[2];
    float qw = cam[3], qx = cam[4], qy = cam[5], qz = cam[6];
    float qn = rsqrtf(qw * qw + qx * qx + qy * qy + qz * qz);
    qw *= qn; qx *= qn; qy *= qn; qz *= qn;
    float r00 = 1.f - 2.f * (qy * qy + qz * qz);
    float r01 = 2.f * (qx * qy - qw * qz);
    float r02 = 2.f * (qx * qz + qw * qy);
    float r10 = 2.f * (qx * qy + qw * qz);
    float r11 = 1.f - 2.f * (qx * qx + qz * qz);
    float r12 = 2.f * (qy * qz - qw * qx);

    // ---- transform all vertices into smem (projected, y-flip folded in)
    for (int n = t; n < NVERT; n += 128) {
        const float* v = verts + (size_t)(b * NVERT + n) * 3;
        float X = v[0], Y = v[1], Z = v[2];
        float xr = r00 * X + r01 * Y + r02 * Z;
        float yr = r10 * X + r11 * Y + r12 * Z;
        sx[n] = s * xr + tx;
        sy[n] = -(s * yr + ty);
    }

    // ---- per-pixel setup
    const int row = tile * 2 + (t >> 6);
    const int xs  = (t & 63) * 4;
    const float inv = 2.0f / (float)IMG;
    const float py = ((float)row + 0.5f) * inv - 1.0f;

    float px[4], acc[4];
#pragma unroll
    for (int p = 0; p < 4; ++p) {
        px[p]  = ((float)(xs + p) + 0.5f) * inv - 1.0f;
        acc[p] = -3.402823466e+38f;
    }

    __syncthreads();   // sx/sy ready

    const int* fbase = faces + (size_t)b * NFACE * 3;

    bool done = false;
    for (int c = 0; c < NFACE; c += FCHUNK) {
        // ---- lazy coefficient computation: 96 threads, one edge each
        if (t < 3 * FCHUNK) {
            const int f = t / 3;        // face within chunk
            const int e = t - 3 * f;    // edge 0,1,2
            const int* fi = fbase + (size_t)(c + f) * 3;
            int ia = fi[e];
            int ib = fi[(e == 2) ? 0 : e + 1];
            float ax = sx[ia], ay = sy[ia];
            float bx = sx[ib], by = sy[ib];
            float ex = bx - ax;
            float ey = by - ay;
            float il = rsqrtf(ex * ex + ey * ey + 1e-12f);
            float exn = ex * il;
            float eyn = ey * il;
            float A = -eyn;
            float B = exn;
            float C = eyn * ax - exn * ay;
            if (e == 0) {
                sf0[f].x = A; sf0[f].y = B; sf0[f].z = C;
                // orient from full triangle (this thread also has i2 via fi)
                int i2 = fi[2];
                float x2 = sx[i2], y2 = sy[i2];
                float area2 = ex * (y2 - ay) - ey * (x2 - ax);
                sf2[f].y = (area2 > 0.f) ? 1.f : ((area2 < 0.f) ? -1.f : 0.f);
            } else if (e == 1) {
                sf0[f].w = A; sf1[f].x = B; sf1[f].y = C;
            } else {
                sf1[f].z = A; sf1[f].w = B; sf2[f].x = C;
            }
        }
        __syncthreads();

        if (!done) {
#pragma unroll 2
            for (int f = 0; f < FCHUNK; ++f) {
                float4 e0 = sf0[f];
                float4 e1 = sf1[f];
                float2 e2 = sf2[f];
                float t1 = fmaf(e0.y, py, e0.z);   // B1*py + C1
                float t2 = fmaf(e1.x, py, e1.y);   // B2*py + C2
                float t3 = fmaf(e1.w, py, e2.x);   // B3*py + C3
                float o  = e2.y;
#pragma unroll
                for (int p = 0; p < 4; ++p) {
                    float d1 = fmaf(e0.x, px[p], t1);
                    float d2 = fmaf(e0.w, px[p], t2);
                    float d3 = fmaf(e1.z, px[p], t3);
                    float dm = fminf(fminf(d1, d2), d3);
                    acc[p] = fmaxf(acc[p], o * dm);
                }
            }
            // saturation: once all 4 accs >= TAU, sigmoid is 1 - <=1.3e-9;
            // remaining faces can only raise the max -> output fixed.
            float m = fminf(fminf(acc[0], acc[1]), fminf(acc[2], acc[3]));
            done = (m >= TAU);
        }
        // block-collective exit; also the barrier protecting sf* reuse
        if (__syncthreads_and(done ? 1 : 0)) break;
    }

    float4 res;
    res.x = 1.0f / (1.0f + expf(-SHARP * acc[0]));
    res.y = 1.0f / (1.0f + expf(-SHARP * acc[1]));
    res.z = 1.0f / (1.0f + expf(-SHARP * acc[2]));
    res.w = 1.0f / (1.0f + expf(-SHARP * acc[3]));

    float4* op = (float4*)(out + (size_t)b * IMG * IMG + (size_t)row * IMG + xs);
    *op = res;
}

extern "C" void kernel_launch(void* const* d_in, const int* in_sizes, int n_in,
                              void* d_out, int out_size) {
    const float* verts = (const float*)d_in[0];  // [2, 642, 3] f32
    const int*   faces = (const int*)d_in[1];    // [2, 1280, 3] i32
    const float* cams  = (const float*)d_in[2];  // [2, 7] f32
    float* out = (float*)d_out;                  // [2, 256, 256] f32

    fused_kernel<<<dim3(IMG * IMG / 512, NBATCH), 128>>>(verts, faces, cams, out);
}